// round 2
// baseline (speedup 1.0000x reference)
#include <cuda_runtime.h>
#include <math.h>

// Problem constants (fixed shapes from reference)
#define BB 8
#define NN 256
#define DD 128
#define NE (BB*NN*NN)          // 524288 edges
#define ROWS (BB*NN)           // 2048
#define TI 8                   // rows per block in K2
#define NB2 (ROWS/TI)          // 256 blocks in K2
#define BN_EPS 1e-5f

// Scratch (static __device__ — no allocation)
__device__ float g_w[NE];            // edge softmax weights (2 MB)
__device__ float g_x[ROWS*DD];       // pre-BN linear+relu output (1 MB)
__device__ float g_psum[NB2*DD];     // per-block BN partial sums
__device__ float g_psq[NB2*DD];      // per-block BN partial sum-of-squares
__device__ float g_scale[DD];        // folded BN scale
__device__ float g_shift[DD];        // folded BN shift

// ---------------------------------------------------------------------------
// K1: per-edge L2 norm over d=128 + passthrough copy of e into the output.
// One warp handles 4 edges; each lane holds one float4 per edge (32*4=128 f).
// Reads 268 MB, writes 268 MB + 2 MB. This kernel IS the runtime.
// ---------------------------------------------------------------------------
__global__ void __launch_bounds__(256) k1_norm_copy(
    const float4* __restrict__ e4, float4* __restrict__ oute4)
{
    int warp = (blockIdx.x * blockDim.x + threadIdx.x) >> 5;
    int lane = threadIdx.x & 31;
    int edge0 = warp * 4;                    // 4 edges per warp

    float4 v[4];
#pragma unroll
    for (int k = 0; k < 4; k++)
        v[k] = e4[(size_t)(edge0 + k) * 32 + lane];   // MLP=4 front-batched
#pragma unroll
    for (int k = 0; k < 4; k++)
        oute4[(size_t)(edge0 + k) * 32 + lane] = v[k];
#pragma unroll
    for (int k = 0; k < 4; k++) {
        float s = v[k].x*v[k].x + v[k].y*v[k].y + v[k].z*v[k].z + v[k].w*v[k].w;
#pragma unroll
        for (int o = 16; o; o >>= 1)
            s += __shfl_xor_sync(0xffffffffu, s, o);
        if (lane == 0) g_w[edge0 + k] = sqrtf(s);
    }
}

// ---------------------------------------------------------------------------
// K2: for a tile of TI=8 consecutive rows (same batch b):
//   softmax over the 256 edge weights per row (warp-level),
//   agg[r,d] = sum_j p[r,j] * h[b,j,d]   (h row read once, reused for 8 rows),
//   s = h + agg, y = relu(s @ W^T + bias),
//   write y to g_x and per-block BN partials.
// 128 threads: thread t = feature channel (agg) = output channel (linear).
// ---------------------------------------------------------------------------
__global__ void __launch_bounds__(128) k2_agg_linear(
    const float* __restrict__ h, const float* __restrict__ W,
    const float* __restrict__ bias)
{
    __shared__ float sw[TI * NN];   // 8 KB: edge weights -> softmax probs
    __shared__ float ss[TI * DD];   // 4 KB: h + agg

    const int t   = threadIdx.x;          // 0..127
    const int blk = blockIdx.x;           // 0..255
    const int gi0 = blk * TI;             // first global row
    const int b   = gi0 / NN;             // batch (TI divides NN)
    const int i0  = gi0 - b * NN;         // local row within batch

    // Load 8 rows x 256 weights into smem (coalesced)
    const float* wsrc = g_w + (size_t)gi0 * NN;
#pragma unroll
    for (int k = 0; k < TI * NN / 128; k++)
        sw[t + 128 * k] = wsrc[t + 128 * k];
    __syncthreads();

    // Warp-level softmax: warp wi handles rows 2wi and 2wi+1
    {
        const int wi = t >> 5, lane = t & 31;
#pragma unroll
        for (int rr = 0; rr < 2; rr++) {
            const int r = wi * 2 + rr;
            float v[8];
            float m = -1e30f;
#pragma unroll
            for (int q = 0; q < 8; q++) {
                v[q] = sw[r * NN + lane + 32 * q];
                m = fmaxf(m, v[q]);
            }
#pragma unroll
            for (int o = 16; o; o >>= 1)
                m = fmaxf(m, __shfl_xor_sync(0xffffffffu, m, o));
            float s = 0.f;
#pragma unroll
            for (int q = 0; q < 8; q++) { v[q] = __expf(v[q] - m); s += v[q]; }
#pragma unroll
            for (int o = 16; o; o >>= 1)
                s += __shfl_xor_sync(0xffffffffu, s, o);
            const float inv = 1.0f / s;
#pragma unroll
            for (int q = 0; q < 8; q++)
                sw[r * NN + lane + 32 * q] = v[q] * inv;
        }
    }
    __syncthreads();

    // Aggregation: acc[r] = sum_j p[r,j] * h[b,j,t]
    float acc[TI];
#pragma unroll
    for (int r = 0; r < TI; r++) acc[r] = 0.f;

    const float* hb = h + (size_t)b * NN * DD;
    for (int j = 0; j < NN; j += 4) {
        const float hv0 = hb[(j + 0) * DD + t];
        const float hv1 = hb[(j + 1) * DD + t];
        const float hv2 = hb[(j + 2) * DD + t];
        const float hv3 = hb[(j + 3) * DD + t];
#pragma unroll
        for (int r = 0; r < TI; r++) {
            const float4 p = *(const float4*)&sw[r * NN + j];
            acc[r] += p.x * hv0 + p.y * hv1 + p.z * hv2 + p.w * hv3;
        }
    }

    // s = h + agg into smem
#pragma unroll
    for (int r = 0; r < TI; r++)
        ss[r * DD + t] = hb[(i0 + r) * DD + t] + acc[r];
    __syncthreads();

    // Linear + ReLU: thread t = output channel k; y[r] = s[r,:] . W[t,:] + b[t]
    float y[TI];
    const float bk = bias[t];
#pragma unroll
    for (int r = 0; r < TI; r++) y[r] = bk;

    const float* wrow = W + (size_t)t * DD;
    for (int d = 0; d < DD; d += 4) {
        const float4 wv = *(const float4*)&wrow[d];
#pragma unroll
        for (int r = 0; r < TI; r++) {
            const float4 sv = *(const float4*)&ss[r * DD + d];
            y[r] += sv.x * wv.x + sv.y * wv.y + sv.z * wv.z + sv.w * wv.w;
        }
    }

    float ps = 0.f, pq = 0.f;
#pragma unroll
    for (int r = 0; r < TI; r++) {
        const float v = fmaxf(y[r], 0.f);
        g_x[(size_t)(gi0 + r) * DD + t] = v;
        ps += v;
        pq += v * v;
    }
    g_psum[blk * DD + t] = ps;
    g_psq [blk * DD + t] = pq;
}

// ---------------------------------------------------------------------------
// K3: deterministic BN stat reduction over the 256 block partials,
// fold gamma/beta/mean/istd into scale+shift. 1 block, 128 threads.
// ---------------------------------------------------------------------------
__global__ void __launch_bounds__(128) k3_bn_stats(
    const float* __restrict__ gamma, const float* __restrict__ beta)
{
    const int t = threadIdx.x;
    float s = 0.f, q = 0.f;
    for (int bl = 0; bl < NB2; bl++) {
        s += g_psum[bl * DD + t];
        q += g_psq [bl * DD + t];
    }
    const float inv_n = 1.0f / (float)ROWS;
    const float mean = s * inv_n;
    const float var  = q * inv_n - mean * mean;    // biased variance
    const float istd = rsqrtf(var + BN_EPS);
    const float sc   = gamma[t] * istd;
    g_scale[t] = sc;
    g_shift[t] = beta[t] - mean * sc;
}

// ---------------------------------------------------------------------------
// K4: out_h = g_x * scale + shift + h   (float4, 65536 vec-elements)
// ---------------------------------------------------------------------------
__global__ void __launch_bounds__(256) k4_finalize(
    const float4* __restrict__ h4, float4* __restrict__ out4)
{
    const int i = blockIdx.x * blockDim.x + threadIdx.x;   // 0..65535
    const float4 x  = ((const float4*)g_x)[i];
    const float4 hv = h4[i];
    const int c = (i * 4) & (DD - 1);
    const float4 sc = *(const float4*)&g_scale[c];
    const float4 sh = *(const float4*)&g_shift[c];
    float4 o;
    o.x = x.x * sc.x + sh.x + hv.x;
    o.y = x.y * sc.y + sh.y + hv.y;
    o.z = x.z * sc.z + sh.z + hv.z;
    o.w = x.w * sc.w + sh.w + hv.w;
    out4[i] = o;
}

// ---------------------------------------------------------------------------
// Launch. Inputs (metadata order): h, e, W, b, gamma, beta.
// Output: [h_new (2048*128 f32)] ++ [e (8*256*256*128 f32)].
// ---------------------------------------------------------------------------
extern "C" void kernel_launch(void* const* d_in, const int* in_sizes, int n_in,
                              void* d_out, int out_size)
{
    const float* h     = (const float*)d_in[0];
    const float* e     = (const float*)d_in[1];
    const float* W     = (const float*)d_in[2];
    const float* bias  = (const float*)d_in[3];
    const float* gamma = (const float*)d_in[4];
    const float* beta  = (const float*)d_in[5];

    float* out_h = (float*)d_out;
    float* out_e = (float*)d_out + (size_t)ROWS * DD;

    // K1: 524288 edges / 4 per warp = 131072 warps; 8 warps/block -> 16384 blocks
    k1_norm_copy<<<NE / 4 / 8, 256>>>((const float4*)e, (float4*)out_e);

    // K2: 256 blocks x 128 threads
    k2_agg_linear<<<NB2, 128>>>(h, W, bias);

    // K3: single block
    k3_bn_stats<<<1, 128>>>(gamma, beta);

    // K4: 65536 float4 / 256 = 256 blocks
    k4_finalize<<<ROWS * DD / 4 / 256, 256>>>((const float4*)h, (float4*)d_out);
}

// round 3
// speedup vs baseline: 1.2207x; 1.2207x over previous
#include <cuda_runtime.h>
#include <math.h>

// Problem constants (fixed shapes from reference)
#define BB 8
#define NN 256
#define DD 128
#define NE (BB*NN*NN)          // 524288 edges
#define ROWS (BB*NN)           // 2048
#define TI 8                   // rows per block in K2
#define NB2 (ROWS/TI)          // 256 blocks in K2
#define BN_EPS 1e-5f

// Scratch (static __device__ — no allocation)
__device__ float g_w[NE];            // edge softmax weights (2 MB)
__device__ float g_x[ROWS*DD];       // pre-BN linear+relu output (1 MB)
__device__ float g_psum[DD*NB2];     // per-block BN partial sums (CHANNEL-MAJOR)
__device__ float g_psq[DD*NB2];      // per-block BN partial sum-of-squares
__device__ float g_scale[DD];        // folded BN scale
__device__ float g_shift[DD];        // folded BN shift

// ---------------------------------------------------------------------------
// K1: per-edge L2 norm over d=128 + passthrough copy of e into the output.
// One warp handles 8 edges (8 LDG.128 in flight per warp). Streaming cache
// hints on both directions (data is touched exactly once). Coalesced 32B
// norm writes from lanes 0-7.
// ---------------------------------------------------------------------------
__global__ void __launch_bounds__(256) k1_norm_copy(
    const float4* __restrict__ e4, float4* __restrict__ oute4)
{
    const int warp  = (blockIdx.x * blockDim.x + threadIdx.x) >> 5;
    const int lane  = threadIdx.x & 31;
    const size_t edge0 = (size_t)warp * 8;          // 8 edges per warp

    float4 v[8];
#pragma unroll
    for (int k = 0; k < 8; k++)
        v[k] = __ldcs(&e4[(edge0 + k) * 32 + lane]);   // front-batched MLP=8
#pragma unroll
    for (int k = 0; k < 8; k++)
        __stcs(&oute4[(edge0 + k) * 32 + lane], v[k]);

    float s[8];
#pragma unroll
    for (int k = 0; k < 8; k++) {
        s[k] = v[k].x*v[k].x + v[k].y*v[k].y + v[k].z*v[k].z + v[k].w*v[k].w;
#pragma unroll
        for (int o = 16; o; o >>= 1)
            s[k] += __shfl_xor_sync(0xffffffffu, s[k], o);
    }
    // lane L (< 8) writes norm of edge L: coalesced 32B store per warp
    float mine = s[0];
#pragma unroll
    for (int k = 1; k < 8; k++)
        mine = (lane == k) ? s[k] : mine;
    if (lane < 8)
        g_w[edge0 + lane] = sqrtf(mine);
}

// ---------------------------------------------------------------------------
// K2: per tile of TI=8 consecutive rows (same batch b):
//   softmax over the 256 edge weights per row (warp-level),
//   agg[r,d] = sum_j p[r,j] * h[b,j,d]   (h row read once, reused x8),
//   s = h + agg, y = relu(s @ W^T + bias),
//   write y to g_x and channel-major per-block BN partials.
// ---------------------------------------------------------------------------
__global__ void __launch_bounds__(128) k2_agg_linear(
    const float* __restrict__ h, const float* __restrict__ W,
    const float* __restrict__ bias)
{
    __shared__ float sw[TI * NN];   // 8 KB: edge weights -> softmax probs
    __shared__ float ss[TI * DD];   // 4 KB: h + agg

    const int t   = threadIdx.x;          // 0..127
    const int blk = blockIdx.x;           // 0..255
    const int gi0 = blk * TI;             // first global row
    const int b   = gi0 / NN;             // batch (TI divides NN)
    const int i0  = gi0 - b * NN;         // local row within batch

    // Load 8 rows x 256 weights into smem (coalesced)
    const float* wsrc = g_w + (size_t)gi0 * NN;
#pragma unroll
    for (int k = 0; k < TI * NN / 128; k++)
        sw[t + 128 * k] = wsrc[t + 128 * k];
    __syncthreads();

    // Warp-level softmax: warp wi handles rows 2wi and 2wi+1
    {
        const int wi = t >> 5, lane = t & 31;
#pragma unroll
        for (int rr = 0; rr < 2; rr++) {
            const int r = wi * 2 + rr;
            float v[8];
            float m = -1e30f;
#pragma unroll
            for (int q = 0; q < 8; q++) {
                v[q] = sw[r * NN + lane + 32 * q];
                m = fmaxf(m, v[q]);
            }
#pragma unroll
            for (int o = 16; o; o >>= 1)
                m = fmaxf(m, __shfl_xor_sync(0xffffffffu, m, o));
            float s = 0.f;
#pragma unroll
            for (int q = 0; q < 8; q++) { v[q] = __expf(v[q] - m); s += v[q]; }
#pragma unroll
            for (int o = 16; o; o >>= 1)
                s += __shfl_xor_sync(0xffffffffu, s, o);
            const float inv = 1.0f / s;
#pragma unroll
            for (int q = 0; q < 8; q++)
                sw[r * NN + lane + 32 * q] = v[q] * inv;
        }
    }
    __syncthreads();

    // Aggregation: acc[r] = sum_j p[r,j] * h[b,j,t]
    float acc[TI];
#pragma unroll
    for (int r = 0; r < TI; r++) acc[r] = 0.f;

    const float* hb = h + (size_t)b * NN * DD;
    for (int j = 0; j < NN; j += 4) {
        const float hv0 = hb[(j + 0) * DD + t];
        const float hv1 = hb[(j + 1) * DD + t];
        const float hv2 = hb[(j + 2) * DD + t];
        const float hv3 = hb[(j + 3) * DD + t];
#pragma unroll
        for (int r = 0; r < TI; r++) {
            const float4 p = *(const float4*)&sw[r * NN + j];
            acc[r] += p.x * hv0 + p.y * hv1 + p.z * hv2 + p.w * hv3;
        }
    }

    // s = h + agg into smem
#pragma unroll
    for (int r = 0; r < TI; r++)
        ss[r * DD + t] = hb[(i0 + r) * DD + t] + acc[r];
    __syncthreads();

    // Linear + ReLU: thread t = output channel k; y[r] = s[r,:] . W[t,:] + b[t]
    float y[TI];
    const float bk = bias[t];
#pragma unroll
    for (int r = 0; r < TI; r++) y[r] = bk;

    const float* wrow = W + (size_t)t * DD;
    for (int d = 0; d < DD; d += 4) {
        const float4 wv = *(const float4*)&wrow[d];
#pragma unroll
        for (int r = 0; r < TI; r++) {
            const float4 sv = *(const float4*)&ss[r * DD + d];
            y[r] += sv.x * wv.x + sv.y * wv.y + sv.z * wv.z + sv.w * wv.w;
        }
    }

    float ps = 0.f, pq = 0.f;
#pragma unroll
    for (int r = 0; r < TI; r++) {
        const float v = fmaxf(y[r], 0.f);
        g_x[(size_t)(gi0 + r) * DD + t] = v;
        ps += v;
        pq += v * v;
    }
    // channel-major so K3's per-channel reduction reads contiguously
    g_psum[t * NB2 + blk] = ps;
    g_psq [t * NB2 + blk] = pq;
}

// ---------------------------------------------------------------------------
// K3: one block per channel; 256 threads reduce 256 block-partials
// (coalesced, channel-major layout), fold into scale+shift.
// ---------------------------------------------------------------------------
__global__ void __launch_bounds__(256) k3_bn_stats(
    const float* __restrict__ gamma, const float* __restrict__ beta)
{
    __shared__ float shs[256], shq[256];
    const int c = blockIdx.x;            // channel 0..127
    const int t = threadIdx.x;           // partial 0..255
    shs[t] = g_psum[c * NB2 + t];
    shq[t] = g_psq [c * NB2 + t];
    __syncthreads();
#pragma unroll
    for (int o = 128; o; o >>= 1) {
        if (t < o) { shs[t] += shs[t + o]; shq[t] += shq[t + o]; }
        __syncthreads();
    }
    if (t == 0) {
        const float inv_n = 1.0f / (float)ROWS;
        const float mean = shs[0] * inv_n;
        const float var  = shq[0] * inv_n - mean * mean;   // biased variance
        const float istd = rsqrtf(var + BN_EPS);
        const float sc   = gamma[c] * istd;
        g_scale[c] = sc;
        g_shift[c] = beta[c] - mean * sc;
    }
}

// ---------------------------------------------------------------------------
// K4: out_h = g_x * scale + shift + h   (float4, 65536 vec-elements)
// ---------------------------------------------------------------------------
__global__ void __launch_bounds__(256) k4_finalize(
    const float4* __restrict__ h4, float4* __restrict__ out4)
{
    const int i = blockIdx.x * blockDim.x + threadIdx.x;   // 0..65535
    const float4 x  = ((const float4*)g_x)[i];
    const float4 hv = h4[i];
    const int c = (i * 4) & (DD - 1);
    const float4 sc = *(const float4*)&g_scale[c];
    const float4 sh = *(const float4*)&g_shift[c];
    float4 o;
    o.x = x.x * sc.x + sh.x + hv.x;
    o.y = x.y * sc.y + sh.y + hv.y;
    o.z = x.z * sc.z + sh.z + hv.z;
    o.w = x.w * sc.w + sh.w + hv.w;
    out4[i] = o;
}

// ---------------------------------------------------------------------------
// Launch. Inputs (metadata order): h, e, W, b, gamma, beta.
// Output: [h_new (2048*128 f32)] ++ [e (8*256*256*128 f32)].
// ---------------------------------------------------------------------------
extern "C" void kernel_launch(void* const* d_in, const int* in_sizes, int n_in,
                              void* d_out, int out_size)
{
    const float* h     = (const float*)d_in[0];
    const float* e     = (const float*)d_in[1];
    const float* W     = (const float*)d_in[2];
    const float* bias  = (const float*)d_in[3];
    const float* gamma = (const float*)d_in[4];
    const float* beta  = (const float*)d_in[5];

    float* out_e = (float*)d_out + (size_t)ROWS * DD;

    // K1: 524288 edges / 8 per warp / 8 warps per block = 8192 blocks
    k1_norm_copy<<<NE / 8 / 8, 256>>>((const float4*)e, (float4*)out_e);

    // K2: 256 blocks x 128 threads
    k2_agg_linear<<<NB2, 128>>>(h, W, bias);

    // K3: one block per channel
    k3_bn_stats<<<DD, 256>>>(gamma, beta);

    // K4: 65536 float4 / 256 = 256 blocks
    k4_finalize<<<ROWS * DD / 4 / 256, 256>>>((const float4*)h, (float4*)d_out);
}